// round 5
// baseline (speedup 1.0000x reference)
#include <cuda_runtime.h>
#include <cstdint>

// FLoss: mean((1 - output[i, target[i]])^2), N=16777216 rows, 2 classes.
// d_in[0] = output float32 [N,2]  (128 MB)
// d_in[1] = target int32 [N]      (64 MB)
// d_out   = single float32.
//
// HBM-bound: 192 MB streamed. Single resident wave: 1184 blocks (148 SM x 8)
// x 256 thr = 2048 thr/SM. Grid-stride, 8 rows / iter = 6 independent
// LDG.128. Zeroing fused: device scratch + arrival counter, last block
// writes d_out and resets state (graph-replay safe).

static constexpr int      N_ELEMS = 16777216;
static constexpr int      BLOCK   = 256;
static constexpr int      GRID    = 148 * 8;            // 1184, one full wave
static constexpr int      THREADS = GRID * BLOCK;       // 303104
static constexpr int      NOCT    = N_ELEMS / 8;        // 2097152

__device__ float        g_scratch = 0.0f;
__device__ unsigned int g_count   = 0;

__device__ __forceinline__ float oct_term(float4 o0, float4 o1, int4 t,
                                          float s) {
    float a = (t.x == 0) ? o0.x : o0.y;
    float b = (t.y == 0) ? o0.z : o0.w;
    float c = (t.z == 0) ? o1.x : o1.y;
    float d = (t.w == 0) ? o1.z : o1.w;
    float da = 1.0f - a, db = 1.0f - b, dc = 1.0f - c, dd = 1.0f - d;
    s = fmaf(da, da, s);
    s = fmaf(db, db, s);
    s = fmaf(dc, dc, s);
    s = fmaf(dd, dd, s);
    return s;
}

__global__ __launch_bounds__(BLOCK) void floss_reduce_kernel(
    const float4* __restrict__ out4,   // [N/2]
    const int4*  __restrict__ tgt4,    // [N/4]
    float* __restrict__ result)
{
    int tid = blockIdx.x * BLOCK + threadIdx.x;

    float s0 = 0.0f, s1 = 0.0f;

    for (int i = tid; i < NOCT; i += THREADS) {
        // 6 independent front-batched 16B loads (oct i = rows 8i..8i+7)
        float4 o0 = __ldg(&out4[4 * i + 0]);
        float4 o1 = __ldg(&out4[4 * i + 1]);
        float4 o2 = __ldg(&out4[4 * i + 2]);
        float4 o3 = __ldg(&out4[4 * i + 3]);
        int4   t0 = __ldg(&tgt4[2 * i + 0]);
        int4   t1 = __ldg(&tgt4[2 * i + 1]);

        s0 = oct_term(o0, o1, t0, s0);
        s1 = oct_term(o2, o3, t1, s1);
    }
    float sum = s0 + s1;

    // warp tree reduce
    #pragma unroll
    for (int off = 16; off > 0; off >>= 1)
        sum += __shfl_down_sync(0xFFFFFFFFu, sum, off);

    __shared__ float ws[BLOCK / 32];
    int lane = threadIdx.x & 31;
    int warp = threadIdx.x >> 5;
    if (lane == 0) ws[warp] = sum;
    __syncthreads();

    if (warp == 0) {
        sum = (lane < BLOCK / 32) ? ws[lane] : 0.0f;
        #pragma unroll
        for (int off = 16; off > 0; off >>= 1)
            sum += __shfl_down_sync(0xFFFFFFFFu, sum, off);

        if (lane == 0) {
            // pre-scaled block contribution into device scratch
            atomicAdd(&g_scratch, sum * (1.0f / (float)N_ELEMS));
            __threadfence();
            unsigned int done = atomicAdd(&g_count, 1u);
            if (done == GRID - 1) {
                // all block sums visible; publish and reset for next replay
                result[0] = g_scratch;
                g_scratch = 0.0f;
                g_count   = 0;
            }
        }
    }
}

extern "C" void kernel_launch(void* const* d_in, const int* in_sizes, int n_in,
                              void* d_out, int out_size)
{
    const float4* out4 = (const float4*)d_in[0];
    const int4*   tgt4 = (const int4*)d_in[1];
    float*        res  = (float*)d_out;

    floss_reduce_kernel<<<GRID, BLOCK>>>(out4, tgt4, res);
}

// round 10
// speedup vs baseline: 1.1414x; 1.1414x over previous
#include <cuda_runtime.h>
#include <cstdint>

// FLoss: mean((1 - output[i, target[i]])^2), N=16777216 rows, 2 classes.
// d_in[0] = output float32 [N,2]  (128 MB)
// d_in[1] = target int32 [N]      (64 MB)
// d_out   = single float32.
//
// HBM-bound: 192 MB streamed. R2-proven shape: grid 2368 x 256, grid-stride,
// 3 independent 16B loads per iteration (4 rows), low reg pressure.
// Single-launch: device scratch + arrival counter; last block publishes
// result and resets state (graph-replay safe, deterministic).

static constexpr int N_ELEMS = 16777216;
static constexpr int NQUAD   = N_ELEMS / 4;   // 4 rows per loop iteration
static constexpr int BLOCK   = 256;
static constexpr int GRID    = 148 * 16;      // 2368 blocks (R2 best)

__device__ float        g_scratch = 0.0f;
__device__ unsigned int g_count   = 0;

__global__ __launch_bounds__(BLOCK) void floss_reduce_kernel(
    const float4* __restrict__ out4,   // [N/2] : 2 rows per float4
    const int4*  __restrict__ tgt4,    // [N/4] : 4 targets per int4
    float* __restrict__ result)
{
    float sum = 0.0f;
    int idx    = blockIdx.x * BLOCK + threadIdx.x;
    int stride = GRID * BLOCK;

    for (int i = idx; i < NQUAD; i += stride) {
        float4 o0 = __ldg(&out4[2 * i]);       // rows 4i, 4i+1
        float4 o1 = __ldg(&out4[2 * i + 1]);   // rows 4i+2, 4i+3
        int4   t  = __ldg(&tgt4[i]);

        float a = (t.x == 0) ? o0.x : o0.y;
        float b = (t.y == 0) ? o0.z : o0.w;
        float c = (t.z == 0) ? o1.x : o1.y;
        float d = (t.w == 0) ? o1.z : o1.w;

        float da = 1.0f - a;
        float db = 1.0f - b;
        float dc = 1.0f - c;
        float dd = 1.0f - d;
        sum = fmaf(da, da, sum);
        sum = fmaf(db, db, sum);
        sum = fmaf(dc, dc, sum);
        sum = fmaf(dd, dd, sum);
    }

    // warp tree reduce
    #pragma unroll
    for (int off = 16; off > 0; off >>= 1)
        sum += __shfl_down_sync(0xFFFFFFFFu, sum, off);

    __shared__ float ws[BLOCK / 32];
    int lane = threadIdx.x & 31;
    int warp = threadIdx.x >> 5;
    if (lane == 0) ws[warp] = sum;
    __syncthreads();

    if (warp == 0) {
        sum = (lane < BLOCK / 32) ? ws[lane] : 0.0f;
        #pragma unroll
        for (int off = 16; off > 0; off >>= 1)
            sum += __shfl_down_sync(0xFFFFFFFFu, sum, off);

        if (lane == 0) {
            atomicAdd(&g_scratch, sum * (1.0f / (float)N_ELEMS));
            __threadfence();
            unsigned int done = atomicAdd(&g_count, 1u);
            if (done == GRID - 1) {
                // all block contributions visible; publish + reset for replay
                result[0] = g_scratch;
                g_scratch = 0.0f;
                g_count   = 0;
            }
        }
    }
}

extern "C" void kernel_launch(void* const* d_in, const int* in_sizes, int n_in,
                              void* d_out, int out_size)
{
    const float4* out4 = (const float4*)d_in[0];
    const int4*   tgt4 = (const int4*)d_in[1];
    float*        res  = (float*)d_out;

    floss_reduce_kernel<<<GRID, BLOCK>>>(out4, tgt4, res);
}

// round 11
// speedup vs baseline: 1.1529x; 1.0101x over previous
#include <cuda_runtime.h>
#include <cstdint>

// FLoss: mean((1 - output[i, target[i]])^2), N=16777216 rows, 2 classes.
// d_in[0] = output float32 [N,2]  (128 MB)
// d_in[1] = target int32 [N]      (64 MB)
// d_out   = single float32.
//
// HBM/LTS-bound: 192 MB streamed at the ~6.2 TB/s LTS cap. Proven shape:
// grid-stride, 3 independent 16B loads per iteration (4 rows), low regs.
// Grid 4736 = 32/SM nominal = 4 waves of 8 resident -> finer tail balance.
// Single-launch: device scratch + arrival counter; last block publishes.

static constexpr int N_ELEMS = 16777216;
static constexpr int NQUAD   = N_ELEMS / 4;   // 4 rows per loop iteration
static constexpr int BLOCK   = 256;
static constexpr int GRID    = 148 * 32;      // 4736 blocks, 4 waves

__device__ float        g_scratch = 0.0f;
__device__ unsigned int g_count   = 0;

__global__ __launch_bounds__(BLOCK) void floss_reduce_kernel(
    const float4* __restrict__ out4,   // [N/2] : 2 rows per float4
    const int4*  __restrict__ tgt4,    // [N/4] : 4 targets per int4
    float* __restrict__ result)
{
    float sum = 0.0f;
    int idx    = blockIdx.x * BLOCK + threadIdx.x;
    int stride = GRID * BLOCK;

    for (int i = idx; i < NQUAD; i += stride) {
        float4 o0 = __ldg(&out4[2 * i]);       // rows 4i, 4i+1
        float4 o1 = __ldg(&out4[2 * i + 1]);   // rows 4i+2, 4i+3
        int4   t  = __ldg(&tgt4[i]);

        float a = (t.x == 0) ? o0.x : o0.y;
        float b = (t.y == 0) ? o0.z : o0.w;
        float c = (t.z == 0) ? o1.x : o1.y;
        float d = (t.w == 0) ? o1.z : o1.w;

        float da = 1.0f - a;
        float db = 1.0f - b;
        float dc = 1.0f - c;
        float dd = 1.0f - d;
        sum = fmaf(da, da, sum);
        sum = fmaf(db, db, sum);
        sum = fmaf(dc, dc, sum);
        sum = fmaf(dd, dd, sum);
    }

    // warp tree reduce
    #pragma unroll
    for (int off = 16; off > 0; off >>= 1)
        sum += __shfl_down_sync(0xFFFFFFFFu, sum, off);

    __shared__ float ws[BLOCK / 32];
    int lane = threadIdx.x & 31;
    int warp = threadIdx.x >> 5;
    if (lane == 0) ws[warp] = sum;
    __syncthreads();

    if (warp == 0) {
        sum = (lane < BLOCK / 32) ? ws[lane] : 0.0f;
        #pragma unroll
        for (int off = 16; off > 0; off >>= 1)
            sum += __shfl_down_sync(0xFFFFFFFFu, sum, off);

        if (lane == 0) {
            atomicAdd(&g_scratch, sum * (1.0f / (float)N_ELEMS));
            __threadfence();
            unsigned int done = atomicAdd(&g_count, 1u);
            if (done == GRID - 1) {
                // all block contributions visible; publish + reset for replay
                result[0] = g_scratch;
                g_scratch = 0.0f;
                g_count   = 0;
            }
        }
    }
}

extern "C" void kernel_launch(void* const* d_in, const int* in_sizes, int n_in,
                              void* d_out, int out_size)
{
    const float4* out4 = (const float4*)d_in[0];
    const int4*   tgt4 = (const int4*)d_in[1];
    float*        res  = (float*)d_out;

    floss_reduce_kernel<<<GRID, BLOCK>>>(out4, tgt4, res);
}